// round 11
// baseline (speedup 1.0000x reference)
#include <cuda_runtime.h>
#include <cuda_fp16.h>

// MorphologicalDilation: out[b,ho,wo,f] = max_{k} ( x[b, ho+ki, wo+kj, 0] + w[k, f] )
// x: (16,256,256,1) f32   w: (9,32) f32   out: (16,254,254,32) f32
//
// R11: persistent tiles — grid = 148*12 CTAs (one resident wave), each CTA
// strides over the 16x16x16 tile space: no wave tail, weights loaded once.
// Body = R9 (fp16x2 math, smem dup-packed taps, 1 row/iter, full unroll).

#define H_IN   256
#define W_IN   256
#define NF     32
#define H_OUT  254
#define W_OUT  254
#define TILE_H 16
#define TILE_W 16
#define XS_W   18
#define XS_H   18
#define OSTRIDE (W_OUT * NF)
#define TILES_X 16
#define TILES_Y 16
#define N_TILES (TILES_X * TILES_Y * 16)   // 4096
#define GRID_P  (148 * 12)                  // 1776 persistent CTAs

// One output row for 4 filters (2 half2 lanes): 9 taps, tree max depth 4.
__device__ __forceinline__ float4 win_row(
    const __half2* a, const __half2* b, const __half2* c,
    const __half2 (*wv)[2])
{
    __half2 acc[2];
#pragma unroll
    for (int h = 0; h < 2; ++h) {
        __half2 t0 = __hmax2(__hadd2(a[0], wv[0][h]), __hadd2(a[1], wv[1][h]));
        __half2 t1 = __hmax2(__hadd2(a[2], wv[2][h]), __hadd2(b[0], wv[3][h]));
        __half2 t2 = __hmax2(__hadd2(b[1], wv[4][h]), __hadd2(b[2], wv[5][h]));
        __half2 t3 = __hmax2(__hadd2(c[0], wv[6][h]), __hadd2(c[1], wv[7][h]));
        __half2 t4 = __hadd2(c[2], wv[8][h]);
        acc[h] = __hmax2(__hmax2(__hmax2(t0, t1), __hmax2(t2, t3)), t4);
    }
    float2 f01 = __half22float2(acc[0]);
    float2 f23 = __half22float2(acc[1]);
    return make_float4(f01.x, f01.y, f23.x, f23.y);
}

template<int NR>
__device__ __forceinline__ void do_column(
    const __half2 (*xs)[XS_W], int pos, float* __restrict__ op,
    const __half2 (*wv)[2])
{
    __half2 p[3][3];
#pragma unroll
    for (int r = 0; r < 2; ++r) {
        p[r][0] = xs[r][pos];
        p[r][1] = xs[r][pos + 1];
        p[r][2] = xs[r][pos + 2];
    }

#pragma unroll
    for (int s = 0; s < NR; ++s) {
        const int c = (s + 2) % 3;
        p[c][0] = xs[s + 2][pos];
        p[c][1] = xs[s + 2][pos + 1];
        p[c][2] = xs[s + 2][pos + 2];

        const int r0 = s % 3, r1 = (s + 1) % 3;
        float4 acc = win_row(p[r0], p[r1], p[c], wv);
        *reinterpret_cast<float4*>(op + s * OSTRIDE) = acc;
    }
}

__global__ __launch_bounds__(128, 12)
void dilation_kernel(const float* __restrict__ x,
                     const float* __restrict__ w,
                     float* __restrict__ out)
{
    __shared__ __half2 xs[XS_H][XS_W];

    const int tid   = threadIdx.x;
    const int pos   = tid >> 3;
    const int fbase = (tid & 7) << 2;

    // Weights once per CTA.
    __half2 wv[9][2];
#pragma unroll
    for (int k = 0; k < 9; ++k) {
        float4 q = *reinterpret_cast<const float4*>(&w[k * NF + fbase]);
        wv[k][0] = __floats2half2_rn(q.x, q.y);
        wv[k][1] = __floats2half2_rn(q.z, q.w);
    }

    for (int t = blockIdx.x; t < N_TILES; t += GRID_P) {
        const int b   = t >> 8;
        const int ty  = (t >> 4) & 15;
        const int tx  = t & 15;
        const int wo0 = tx * TILE_W;
        const int ho0 = ty * TILE_H;

        const int nr    = (ty == 15) ? (H_OUT - 15 * TILE_H) : TILE_H; // 14 : 16
        const int nrows = nr + 2;

        __syncthreads();   // previous tile's smem reads complete

        const float* xg = x + (b * H_IN + ho0) * W_IN;
        for (int i = tid; i < nrows * XS_W; i += 128) {
            const int r  = i / XS_W;
            const int c  = i - r * XS_W;
            const int gc = min(wo0 + c, W_IN - 1);
            xs[r][c] = __half2half2(__float2half_rn(xg[r * W_IN + gc]));
        }

        __syncthreads();

        const int wo = wo0 + pos;
        if (wo < W_OUT) {
            float* op = out + ((b * H_OUT + ho0) * W_OUT + wo) * NF + fbase;
            if (nr == TILE_H) do_column<TILE_H>(xs, pos, op, wv);
            else              do_column<H_OUT % TILE_H>(xs, pos, op, wv);
        }
    }
}

extern "C" void kernel_launch(void* const* d_in, const int* in_sizes, int n_in,
                              void* d_out, int out_size)
{
    const float* x = (const float*)d_in[0];
    const float* w = (const float*)d_in[1];
    float* out = (float*)d_out;

    dilation_kernel<<<GRID_P, 128>>>(x, w, out);
}

// round 12
// speedup vs baseline: 1.0870x; 1.0870x over previous
#include <cuda_runtime.h>
#include <cuda_fp16.h>

// MorphologicalDilation: out[b,ho,wo,f] = max_{k} ( x[b, ho+ki, wo+kj, 0] + w[k, f] )
// x: (16,256,256,1) f32   w: (9,32) f32   out: (16,254,254,32) f32
//
// R12: R9 body (fp16x2 smem kernel, best measured) with TILE_H=8 to cut the
// wave tail (8192 CTAs -> 4.6 waves, ~92% wave utilization vs 77%), plus
// single-instruction dup-pack cvt in the fill.

#define H_IN   256
#define W_IN   256
#define NF     32
#define H_OUT  254
#define W_OUT  254
#define TILE_H 8
#define TILE_W 16
#define TILES_Y 32            // ceil(254/8); last tile has 6 rows
#define XS_W   18
#define XS_H   (TILE_H + 2)
#define OSTRIDE (W_OUT * NF)

__device__ __forceinline__ __half2 dup_h2(float x) {
    __half2 d;
    asm("cvt.rn.f16x2.f32 %0, %1, %1;" : "=r"(*reinterpret_cast<unsigned*>(&d)) : "f"(x));
    return d;
}

// One output row for 4 filters (2 half2 lanes): 9 taps, tree max depth 4.
__device__ __forceinline__ float4 win_row(
    const __half2* a, const __half2* b, const __half2* c,
    const __half2 (*wv)[2])
{
    __half2 acc[2];
#pragma unroll
    for (int h = 0; h < 2; ++h) {
        __half2 t0 = __hmax2(__hadd2(a[0], wv[0][h]), __hadd2(a[1], wv[1][h]));
        __half2 t1 = __hmax2(__hadd2(a[2], wv[2][h]), __hadd2(b[0], wv[3][h]));
        __half2 t2 = __hmax2(__hadd2(b[1], wv[4][h]), __hadd2(b[2], wv[5][h]));
        __half2 t3 = __hmax2(__hadd2(c[0], wv[6][h]), __hadd2(c[1], wv[7][h]));
        __half2 t4 = __hadd2(c[2], wv[8][h]);
        acc[h] = __hmax2(__hmax2(__hmax2(t0, t1), __hmax2(t2, t3)), t4);
    }
    float2 f01 = __half22float2(acc[0]);
    float2 f23 = __half22float2(acc[1]);
    return make_float4(f01.x, f01.y, f23.x, f23.y);
}

template<int NR>
__device__ __forceinline__ void do_column(
    const __half2 (*xs)[XS_W], int pos, float* __restrict__ op,
    const __half2 (*wv)[2])
{
    __half2 p[3][3];
#pragma unroll
    for (int r = 0; r < 2; ++r) {
        p[r][0] = xs[r][pos];
        p[r][1] = xs[r][pos + 1];
        p[r][2] = xs[r][pos + 2];
    }

#pragma unroll
    for (int s = 0; s < NR; ++s) {
        const int c = (s + 2) % 3;
        p[c][0] = xs[s + 2][pos];
        p[c][1] = xs[s + 2][pos + 1];
        p[c][2] = xs[s + 2][pos + 2];

        const int r0 = s % 3, r1 = (s + 1) % 3;
        float4 acc = win_row(p[r0], p[r1], p[c], wv);
        *reinterpret_cast<float4*>(op + s * OSTRIDE) = acc;
    }
}

__global__ __launch_bounds__(128, 12)
void dilation_kernel(const float* __restrict__ x,
                     const float* __restrict__ w,
                     float* __restrict__ out)
{
    __shared__ __half2 xs[XS_H][XS_W];   // dup-packed {x,x} taps

    const int tid = threadIdx.x;
    const int wo0 = blockIdx.x * TILE_W;
    const int ho0 = blockIdx.y * TILE_H;
    const int b   = blockIdx.z;

    const int nr    = min(TILE_H, H_OUT - ho0);   // 8, or 6 on last tile row
    const int nrows = nr + 2;

    const float* xg = x + (b * H_IN + ho0) * W_IN;
    for (int i = tid; i < nrows * XS_W; i += 128) {
        const int r  = i / XS_W;
        const int c  = i - r * XS_W;
        const int gc = min(wo0 + c, W_IN - 1);
        xs[r][c] = dup_h2(xg[r * W_IN + gc]);
    }

    const int pos   = tid >> 3;
    const int fbase = (tid & 7) << 2;
    __half2 wv[9][2];
#pragma unroll
    for (int k = 0; k < 9; ++k) {
        float4 q = *reinterpret_cast<const float4*>(&w[k * NF + fbase]);
        wv[k][0] = __floats2half2_rn(q.x, q.y);
        wv[k][1] = __floats2half2_rn(q.z, q.w);
    }

    __syncthreads();

    const int wo = wo0 + pos;
    if (wo >= W_OUT) return;

    float* op = out + ((b * H_OUT + ho0) * W_OUT + wo) * NF + fbase;

    if (nr == TILE_H) do_column<TILE_H>(xs, pos, op, wv);
    else              do_column<H_OUT - (TILES_Y - 1) * TILE_H>(xs, pos, op, wv);  // 6
}

extern "C" void kernel_launch(void* const* d_in, const int* in_sizes, int n_in,
                              void* d_out, int out_size)
{
    const float* x = (const float*)d_in[0];
    const float* w = (const float*)d_in[1];
    float* out = (float*)d_out;

    const int B = in_sizes[0] / (H_IN * W_IN);   // 16

    dim3 grid((W_OUT + TILE_W - 1) / TILE_W, TILES_Y, B);   // (16,32,16) = 8192
    dilation_kernel<<<grid, 128>>>(x, w, out);
}